// round 15
// baseline (speedup 1.0000x reference)
#include <cuda_runtime.h>

// HWnet: B scalar queries vs sorted anchor grid (linspace), 9-pt softmax
// window over vector_table[T=2048, D=64].
//
// R8 (re-bench after infra failure): contention-free counting sort by window
// base + register row reuse.
//  K1 : per-query weights + base        (1 thread / query)
//  KH : per-block smem histogram -> g_cnt[block][bin]
//  KSc: per-bin column scan over blocks -> g_colpre, g_tot
//  KSb: exclusive scan over bins        -> g_binbase
//  KX : scatter via SMEM cursors (smem atomics only, ~0.5 q/bin/block)
//  K4 : half-warp per run of 8 base-sorted queries; 9 window rows cached in
//       registers, reloaded only on base change -> ~8x fewer gather bytes.

#define B_Q    131072
#define T_T    2048
#define D_D    64
#define E_E    4
#define W_W    9
#define NBIN   2048
#define SGRID  128        // blocks for histogram/scatter chunking
#define RUN    8          // sorted queries per half-warp in K4

__device__ float4 g_w03[B_Q];
__device__ float4 g_w47[B_Q];
__device__ float4 g_w8b[B_Q];          // {w8, base(intbits), 0, 0}
__device__ int    g_base[B_Q];
__device__ int    g_cnt[SGRID * NBIN];
__device__ int    g_colpre[SGRID * NBIN];
__device__ int    g_tot[NBIN];
__device__ int    g_binbase[NBIN];
__device__ int    g_sorted[B_Q];

// --------------------------------------------------- K1: per-query weights
__global__ __launch_bounds__(256) void k1_weights(
    const float* __restrict__ x,
    const float* __restrict__ ev,
    const float* __restrict__ tc,
    const int*   __restrict__ idx_tab,
    int nq)
{
    int q = blockIdx.x * blockDim.x + threadIdx.x;
    if (q >= nq) return;

    float xv = __ldg(&x[q]);

    // Uniform-grid guess (ev is linspace), exact +-2 argmin refine with
    // strict-< first-index tie-break (matches reference argmin).
    float e0 = __ldg(&ev[0]);
    float eN = __ldg(&ev[T_T - 1]);
    float inv_step = (float)(T_T - 1) / (eN - e0);
    int g = __float2int_rn((xv - e0) * inv_step);
    g = min(max(g, 0), T_T - 1);

    int lo = max(g - 2, 0), hi = min(g + 2, T_T - 1);
    int nidx = lo;
    float bd = 3.402823466e+38f;
    for (int j = lo; j <= hi; ++j) {
        float d = xv - __ldg(&ev[j]);
        d = d * d;
        if (d < bd) { bd = d; nidx = j; }
    }

    // takecare uses UNCLAMPED nearest idx; window uses clamped.
    float take = __ldg(&tc[nidx]);
    int idx_c = min(max(nidx, E_E), T_T - 1 - E_E);

    float lg[W_W];
    float m = -3.402823466e+38f;
    #pragma unroll
    for (int j = 0; j < W_W; ++j) {
        int w = idx_c + __ldg(&idx_tab[j]);
        float d = xv - __ldg(&ev[w]);
        float l = -(d * d) * take;
        lg[j] = l;
        m = fmaxf(m, l);
    }
    float ssum = 0.0f;
    #pragma unroll
    for (int j = 0; j < W_W; ++j) {
        float e = __expf(lg[j] - m);
        lg[j] = e;
        ssum += e;
    }
    float inv = __frcp_rn(ssum);

    g_w03[q] = make_float4(lg[0] * inv, lg[1] * inv, lg[2] * inv, lg[3] * inv);
    g_w47[q] = make_float4(lg[4] * inv, lg[5] * inv, lg[6] * inv, lg[7] * inv);
    g_w8b[q] = make_float4(lg[8] * inv, __int_as_float(idx_c), 0.f, 0.f);
    g_base[q] = idx_c;
}

// -------------------------------------------- KH: per-block smem histogram
__global__ __launch_bounds__(256) void kh_hist(int nq)
{
    __shared__ int sh[NBIN];
    int tid = threadIdx.x;
    for (int i = tid; i < NBIN; i += 256) sh[i] = 0;
    __syncthreads();

    int chunk = (nq + SGRID - 1) / SGRID;
    int q0 = blockIdx.x * chunk;
    int q1 = min(q0 + chunk, nq);
    for (int q = q0 + tid; q < q1; q += 256)
        atomicAdd(&sh[__ldg(&g_base[q])], 1);
    __syncthreads();

    for (int i = tid; i < NBIN; i += 256)
        g_cnt[blockIdx.x * NBIN + i] = sh[i];
}

// ------------------------------- KSc: per-bin scan over blocks (thread=bin)
__global__ __launch_bounds__(256) void ks_col()
{
    int bin = blockIdx.x * blockDim.x + threadIdx.x;  // 2048 threads total
    if (bin >= NBIN) return;
    int sum = 0;
    for (int b = 0; b < SGRID; ++b) {
        int c = g_cnt[b * NBIN + bin];
        g_colpre[b * NBIN + bin] = sum;
        sum += c;
    }
    g_tot[bin] = sum;
}

// ---------------------------------------- KSb: exclusive scan over 2048 bins
__global__ __launch_bounds__(256) void ks_bin()
{
    __shared__ int s_warp[8];
    int t = threadIdx.x;

    int v[8];
    int run = 0;
    #pragma unroll
    for (int j = 0; j < 8; ++j) {
        int tmp = g_tot[t * 8 + j];
        v[j] = run;
        run += tmp;
    }
    int lane = t & 31, w = t >> 5;
    int xi = run;
    #pragma unroll
    for (int d = 1; d < 32; d <<= 1) {
        int y = __shfl_up_sync(0xffffffffu, xi, d);
        if (lane >= d) xi += y;
    }
    if (lane == 31) s_warp[w] = xi;
    __syncthreads();
    if (t == 0) {
        int acc = 0;
        #pragma unroll
        for (int k = 0; k < 8; ++k) { int tmp = s_warp[k]; s_warp[k] = acc; acc += tmp; }
    }
    __syncthreads();
    int thread_excl = (xi - run) + s_warp[w];
    #pragma unroll
    for (int j = 0; j < 8; ++j)
        g_binbase[t * 8 + j] = thread_excl + v[j];
}

// ----------------------------------- KX: scatter via smem cursors (no ATOMG)
__global__ __launch_bounds__(256) void kx_scatter(int nq)
{
    __shared__ int cur[NBIN];
    int tid = threadIdx.x;
    for (int i = tid; i < NBIN; i += 256)
        cur[i] = g_binbase[i] + g_colpre[blockIdx.x * NBIN + i];
    __syncthreads();

    int chunk = (nq + SGRID - 1) / SGRID;
    int q0 = blockIdx.x * chunk;
    int q1 = min(q0 + chunk, nq);
    for (int q = q0 + tid; q < q1; q += 256) {
        int b = __ldg(&g_base[q]);
        int pos = atomicAdd(&cur[b], 1);
        g_sorted[pos] = q;
    }
}

// ------------------------------- K4: gather with register-cached window rows
__global__ __launch_bounds__(256) void k4_compute(
    const float* __restrict__ vec,
    float*       __restrict__ out,
    int nq)
{
    int gt = blockIdx.x * blockDim.x + threadIdx.x;
    int h = gt >> 4;          // half-warp id -> run of RUN sorted positions
    int c = gt & 15;          // float4 chunk of D (fixed per thread)
    int start = h * RUN;
    if (start >= nq) return;

    int cnt = min(RUN, nq - start);
    int cur = -1;
    float4 r0, r1, r2, r3, r4, r5, r6, r7, r8;
    r0 = r1 = r2 = r3 = r4 = r5 = r6 = r7 = r8 = make_float4(0.f, 0.f, 0.f, 0.f);

    #pragma unroll
    for (int i = 0; i < RUN; ++i) {
        if (i >= cnt) break;
        int qid = __ldg(&g_sorted[start + i]);

        float4 w03 = __ldg(&g_w03[qid]);
        float4 w47 = __ldg(&g_w47[qid]);
        float4 w8b = __ldg(&g_w8b[qid]);
        int base = __float_as_int(w8b.y);

        if (base != cur) {
            cur = base;
            const float4* vp =
                reinterpret_cast<const float4*>(vec + (size_t)(base - E_E) * D_D) + c;
            r0 = __ldg(vp + 0 * (D_D / 4));
            r1 = __ldg(vp + 1 * (D_D / 4));
            r2 = __ldg(vp + 2 * (D_D / 4));
            r3 = __ldg(vp + 3 * (D_D / 4));
            r4 = __ldg(vp + 4 * (D_D / 4));
            r5 = __ldg(vp + 5 * (D_D / 4));
            r6 = __ldg(vp + 6 * (D_D / 4));
            r7 = __ldg(vp + 7 * (D_D / 4));
            r8 = __ldg(vp + 8 * (D_D / 4));
        }

        float4 a, b;
        a.x = w03.x * r0.x;            a.y = w03.x * r0.y;
        a.z = w03.x * r0.z;            a.w = w03.x * r0.w;
        b.x = w03.y * r1.x;            b.y = w03.y * r1.y;
        b.z = w03.y * r1.z;            b.w = w03.y * r1.w;
        a.x = fmaf(w03.z, r2.x, a.x);  a.y = fmaf(w03.z, r2.y, a.y);
        a.z = fmaf(w03.z, r2.z, a.z);  a.w = fmaf(w03.z, r2.w, a.w);
        b.x = fmaf(w03.w, r3.x, b.x);  b.y = fmaf(w03.w, r3.y, b.y);
        b.z = fmaf(w03.w, r3.z, b.z);  b.w = fmaf(w03.w, r3.w, b.w);
        a.x = fmaf(w47.x, r4.x, a.x);  a.y = fmaf(w47.x, r4.y, a.y);
        a.z = fmaf(w47.x, r4.z, a.z);  a.w = fmaf(w47.x, r4.w, a.w);
        b.x = fmaf(w47.y, r5.x, b.x);  b.y = fmaf(w47.y, r5.y, b.y);
        b.z = fmaf(w47.y, r5.z, b.z);  b.w = fmaf(w47.y, r5.w, b.w);
        a.x = fmaf(w47.z, r6.x, a.x);  a.y = fmaf(w47.z, r6.y, a.y);
        a.z = fmaf(w47.z, r6.z, a.z);  a.w = fmaf(w47.z, r6.w, a.w);
        b.x = fmaf(w47.w, r7.x, b.x);  b.y = fmaf(w47.w, r7.y, b.y);
        b.z = fmaf(w47.w, r7.z, b.z);  b.w = fmaf(w47.w, r7.w, b.w);
        a.x = fmaf(w8b.x, r8.x, a.x);  a.y = fmaf(w8b.x, r8.y, a.y);
        a.z = fmaf(w8b.x, r8.z, a.z);  a.w = fmaf(w8b.x, r8.w, a.w);

        float4 acc = make_float4(a.x + b.x, a.y + b.y, a.z + b.z, a.w + b.w);
        reinterpret_cast<float4*>(out)[(size_t)qid * 16 + c] = acc;
    }
}

extern "C" void kernel_launch(void* const* d_in, const int* in_sizes, int n_in,
                              void* d_out, int out_size)
{
    const float* x    = (const float*)d_in[0];
    const float* ev   = (const float*)d_in[1];
    const float* tc   = (const float*)d_in[2];
    const float* vec  = (const float*)d_in[3];
    const int*   itab = (const int*)d_in[4];
    float* out = (float*)d_out;

    int nq = in_sizes[0];

    k1_weights<<<(nq + 255) / 256, 256>>>(x, ev, tc, itab, nq);
    kh_hist<<<SGRID, 256>>>(nq);
    ks_col<<<NBIN / 256, 256>>>();
    ks_bin<<<1, 256>>>();
    kx_scatter<<<SGRID, 256>>>(nq);

    int halfwarps = (nq + RUN - 1) / RUN;
    int threads = halfwarps * 16;
    k4_compute<<<(threads + 255) / 256, 256>>>(vec, out, nq);
}